// round 1
// baseline (speedup 1.0000x reference)
#include <cuda_runtime.h>
#include <math.h>

#define NB 64
#define TT 512
#define DD 1024
#define HH 1024
#define FOURH 4096

// Scratch (allocation-free rule: __device__ globals)
__device__ float g_xw[(size_t)NB * TT * FOURH];  // 512 MiB: precomputed x@Wx + b
__device__ float g_c[NB * HH];                   // LSTM cell state

// ---------------------------------------------------------------------------
// zero the cell state
// ---------------------------------------------------------------------------
__global__ void zero_c_kernel(float* __restrict__ c) {
    c[blockIdx.x * 1024 + threadIdx.x] = 0.0f;
}

// ---------------------------------------------------------------------------
// xW GEMM: C[M,N] = A[M,K] @ B[K,N] + bias ; M=32768, K=1024, N=4096
// 128x128 CTA tile, BK=8, 8x8 register tile, 256 threads.
// ---------------------------------------------------------------------------
__global__ __launch_bounds__(256, 2) void xw_gemm_kernel(
    const float* __restrict__ A, const float* __restrict__ B,
    const float* __restrict__ bias, float* __restrict__ C)
{
    const int M = NB * TT, N = FOURH, K = DD;
    __shared__ float As[8][128];
    __shared__ float Bs[8][128];

    const int tid = threadIdx.x;
    const int bx = blockIdx.x;   // N tile
    const int by = blockIdx.y;   // M tile

    const int arow = tid >> 1;            // 0..127
    const int acol = (tid & 1) << 2;      // 0 or 4
    const int brow = tid >> 5;            // 0..7
    const int bcol = (tid & 31) << 2;     // 0..124

    const float* Aptr = A + (size_t)(by * 128 + arow) * K + acol;
    const float* Bptr = B + (size_t)brow * N + bx * 128 + bcol;

    const int ty = (tid >> 4) << 3;       // 0..120
    const int tx = (tid & 15) << 3;       // 0..120

    float acc[8][8];
    #pragma unroll
    for (int i = 0; i < 8; i++)
        #pragma unroll
        for (int j = 0; j < 8; j++) acc[i][j] = 0.0f;

    float ra[8], rb[8];

    for (int k0 = 0; k0 < K; k0 += 8) {
        float4 av = *(const float4*)Aptr;  Aptr += 8;
        float4 bv = *(const float4*)Bptr;  Bptr += (size_t)8 * N;

        __syncthreads();
        As[acol + 0][arow] = av.x;
        As[acol + 1][arow] = av.y;
        As[acol + 2][arow] = av.z;
        As[acol + 3][arow] = av.w;
        *(float4*)&Bs[brow][bcol] = bv;
        __syncthreads();

        #pragma unroll
        for (int k = 0; k < 8; k++) {
            *(float4*)&ra[0] = *(const float4*)&As[k][ty];
            *(float4*)&ra[4] = *(const float4*)&As[k][ty + 4];
            *(float4*)&rb[0] = *(const float4*)&Bs[k][tx];
            *(float4*)&rb[4] = *(const float4*)&Bs[k][tx + 4];
            #pragma unroll
            for (int i = 0; i < 8; i++)
                #pragma unroll
                for (int j = 0; j < 8; j++)
                    acc[i][j] += ra[i] * rb[j];
        }
    }

    // epilogue: add bias, store
    float bv0[8];
    #pragma unroll
    for (int j = 0; j < 8; j++) bv0[j] = bias[bx * 128 + tx + j];

    #pragma unroll
    for (int i = 0; i < 8; i++) {
        float* crow = C + (size_t)(by * 128 + ty + i) * N + bx * 128 + tx;
        float4 v0, v1;
        v0.x = acc[i][0] + bv0[0]; v0.y = acc[i][1] + bv0[1];
        v0.z = acc[i][2] + bv0[2]; v0.w = acc[i][3] + bv0[3];
        v1.x = acc[i][4] + bv0[4]; v1.y = acc[i][5] + bv0[5];
        v1.z = acc[i][6] + bv0[6]; v1.w = acc[i][7] + bv0[7];
        *(float4*)&crow[0] = v0;
        *(float4*)&crow[4] = v1;
    }
}

// ---------------------------------------------------------------------------
// One LSTM timestep.
//   grid = (64 jh-blocks, 2 n-blocks), 256 threads.
//   Each CTA: n in [nb*32, nb*32+32), jh in [jb*16, jb*16+16).
//   Computes a[n][g*H + jh] = xw + h_{t-1} @ Wh for the 64 columns
//   {g*1024 + jb*16 + jj}, then gates + c/h update.
// ---------------------------------------------------------------------------
__global__ __launch_bounds__(256) void lstm_step_kernel(
    const float* __restrict__ hprev, int hstride,      // h_{t-1}[n*hstride + k]
    const float* __restrict__ Wh,                      // (1024, 4096)
    const float* __restrict__ xw,                      // g_xw + t*4096; n-stride TT*4096
    float* __restrict__ outp,                          // d_out + t*1024; n-stride TT*1024
    float* __restrict__ cst)                           // (64, 1024)
{
    __shared__ float whs[16][64];      // Wh tile: [kr][local col l = g*16+jj]
    __shared__ float hs[16][33];       // h tile transposed (padded)
    __shared__ float as_[32][80];      // preactivations (padded, stride 80)

    const int tid = threadIdx.x;
    const int jb = blockIdx.x;     // 0..63
    const int nb = blockIdx.y;     // 0..1

    const int lx = tid & 15;       // l-group: l = lx*4..lx*4+3
    const int ly = tid >> 4;       // n-group: n = ly*2, ly*2+1

    // Wh tile load mapping: 16 k-rows x 16 float4 chunks
    const int wkr = tid >> 4;                  // 0..15
    const int wch = tid & 15;                  // 0..15
    const int wg  = wch >> 2;                  // gate 0..3
    const int wq  = wch & 3;                   // float4 group within 16 cols
    const size_t wcol = (size_t)wg * 1024 + jb * 16 + wq * 4;

    // h tile load mapping: 32 n x 8 k-pairs
    const int hn = tid >> 3;                   // 0..31
    const int hk = (tid & 7) << 1;             // 0,2,...,14
    const float* hrow = hprev + (size_t)(nb * 32 + hn) * hstride;

    float acc[2][4] = {{0.f,0.f,0.f,0.f},{0.f,0.f,0.f,0.f}};

    for (int k0 = 0; k0 < HH; k0 += 16) {
        float4 wv = *(const float4*)(Wh + (size_t)(k0 + wkr) * FOURH + wcol);
        float2 hv = *(const float2*)(hrow + k0 + hk);

        __syncthreads();
        *(float4*)&whs[wkr][wch * 4] = wv;
        hs[hk][hn]     = hv.x;
        hs[hk + 1][hn] = hv.y;
        __syncthreads();

        #pragma unroll
        for (int kr = 0; kr < 16; kr++) {
            float hr0 = hs[kr][ly * 2];
            float hr1 = hs[kr][ly * 2 + 1];
            float4 w = *(const float4*)&whs[kr][lx * 4];
            acc[0][0] += hr0 * w.x; acc[0][1] += hr0 * w.y;
            acc[0][2] += hr0 * w.z; acc[0][3] += hr0 * w.w;
            acc[1][0] += hr1 * w.x; acc[1][1] += hr1 * w.y;
            acc[1][2] += hr1 * w.z; acc[1][3] += hr1 * w.w;
        }
    }

    __syncthreads();
    // add xw projection, stage preactivations in shared
    #pragma unroll
    for (int i = 0; i < 2; i++) {
        const int n = ly * 2 + i;
        const float* xwrow = xw + (size_t)(nb * 32 + n) * ((size_t)TT * FOURH);
        #pragma unroll
        for (int j = 0; j < 4; j++) {
            const int l = lx * 4 + j;
            const int col = (l >> 4) * 1024 + jb * 16 + (l & 15);
            as_[n][l] = acc[i][j] + xwrow[col];
        }
    }
    __syncthreads();

    // gates + state update: 512 (n,jj) pairs, 2 per thread
    #pragma unroll
    for (int i = 0; i < 2; i++) {
        const int p = tid + i * 256;
        const int n = p >> 4;          // 0..31
        const int jj = p & 15;         // 0..15

        const float ai = as_[n][jj];
        const float af = as_[n][16 + jj];
        const float ao = as_[n][32 + jj];
        const float ag = as_[n][48 + jj];

        const float ig = 1.0f / (1.0f + __expf(-ai));
        const float fg = 1.0f / (1.0f + __expf(-af));
        const float og = 1.0f / (1.0f + __expf(-ao));
        const float gg = 2.0f / (1.0f + __expf(-2.0f * ag)) - 1.0f;

        const size_t cidx = (size_t)(nb * 32 + n) * HH + jb * 16 + jj;
        const float cv = fg * cst[cidx] + ig * gg;
        cst[cidx] = cv;
        const float th = 2.0f / (1.0f + __expf(-2.0f * cv)) - 1.0f;
        outp[(size_t)(nb * 32 + n) * ((size_t)TT * HH) + jb * 16 + jj] = og * th;
    }
}

// ---------------------------------------------------------------------------
extern "C" void kernel_launch(void* const* d_in, const int* in_sizes, int n_in,
                              void* d_out, int out_size)
{
    const float* x  = (const float*)d_in[0];   // (64, 512, 1024)
    const float* h0 = (const float*)d_in[1];   // (64, 1024)
    const float* Wx = (const float*)d_in[2];   // (1024, 4096)
    const float* Wh = (const float*)d_in[3];   // (1024, 4096)
    const float* b  = (const float*)d_in[4];   // (4096,)
    float* out = (float*)d_out;                // (64, 512, 1024)

    float* xw = nullptr;
    float* cst = nullptr;
    cudaGetSymbolAddress((void**)&xw, g_xw);
    cudaGetSymbolAddress((void**)&cst, g_c);

    // 1. zero cell state
    zero_c_kernel<<<NB, 1024>>>(cst);

    // 2. precompute xW = x @ Wx + b  (fully parallel GEMM)
    {
        dim3 grid(FOURH / 128, (NB * TT) / 128);
        xw_gemm_kernel<<<grid, 256>>>(x, Wx, b, xw);
    }

    // 3. 512 sequential timesteps
    for (int t = 0; t < TT; t++) {
        const float* hprev = (t == 0) ? h0 : (out + (size_t)(t - 1) * HH);
        const int hstride  = (t == 0) ? HH : (TT * HH);
        lstm_step_kernel<<<dim3(64, 2), 256>>>(
            hprev, hstride, Wh,
            xw + (size_t)t * FOURH,
            out + (size_t)t * HH,
            cst);
    }
}